// round 2
// baseline (speedup 1.0000x reference)
#include <cuda_runtime.h>

#define EPS 1e-10f
#define NSTATE 68
#define ROWPAD 69              // 69 mod 32 = 5, gcd(5,32)=1 -> conflict-free row reads
#define WARPS_PER_BLOCK 4
#define THREADS (WARPS_PER_BLOCK * 32)
#define FLOATS_PER_WARP (32 * NSTATE)   // 2176

// Derived-constant block: [0..74] raw params, [75..80] precomputed composites.
__device__ float g_const[88];

__global__ void setup_consts_kernel(const float* __restrict__ params) {
    int i = threadIdx.x;
    if (i < 75) g_const[i] = params[i];
    if (i == 75) {
        // kBRAF_eff = ka1 * IC50^n / (IC50^n + Vem^n + EPS)
        float hill  = params[62];
        float ic50n = powf(params[61], hill);
        float vemn  = powf(params[57], hill);
        g_const[75] = params[0] * ic50n / (ic50n + vemn + EPS);
    }
    if (i == 76) {
        // tram_ksr = K^n / (K^n + T^n + EPS)
        float nt  = params[56];
        float ktn = powf(params[55], nt);
        float tn  = powf(params[53], nt);
        g_const[76] = ktn / (ktn + tn + EPS);
    }
    if (i == 77) g_const[77] = params[27] / (params[22] + EPS);  // km_Dusp ratio
    if (i == 78) g_const[78] = params[28] / (params[23] + EPS);  // km_Sprty ratio
    if (i == 79) g_const[79] = params[58] * params[57];          // kDimerForm * Vem
    if (i == 80) g_const[80] = params[60] * params[57];          // kParadoxCRAF * Vem
}

__global__ __launch_bounds__(THREADS)
void mapk_rhs_kernel(const float* __restrict__ y, float* __restrict__ out, int n) {
    __shared__ float stage[WARPS_PER_BLOCK][32 * ROWPAD];

    const int lane = threadIdx.x & 31;
    const int warp = threadIdx.x >> 5;
    const int rowStart = blockIdx.x * THREADS + warp * 32;
    if (rowStart >= n) return;
    const int rowsHere = min(32, n - rowStart);
    const int nf = rowsHere * NSTATE;

    float* s = stage[warp];

    // ---- Phase 1: coalesced global -> smem (clip at staging) ----
    {
        const float* gsrc = y + (size_t)rowStart * NSTATE;
        #pragma unroll 4
        for (int f = lane; f < FLOATS_PER_WARP; f += 32) {
            if (f < nf) {
                int r = f / NSTATE;
                int c = f - r * NSTATE;
                s[r * ROWPAD + c] = fmaxf(__ldg(&gsrc[f]), 0.0f);
            }
        }
    }
    __syncwarp();

    // ---- Phase 2: per-thread row compute (conflict-free smem row access) ----
    if (lane < rowsHere) {
        float* sr = s + lane * ROWPAD;
        float ys[NSTATE];
        #pragma unroll
        for (int i = 0; i < NSTATE; i++) ys[i] = sr[i];

        const float ka1            = g_const[0];
        const float kr1            = g_const[1];
        const float kc1            = g_const[2];
        const float kpCraf         = g_const[3];
        const float kpMek          = g_const[4];
        const float kpErk          = g_const[5];
        const float kDegradEgfr    = g_const[6];
        const float kErkInbEgfr    = g_const[7];
        const float kShcDephos     = g_const[8];
        const float kptpDeg        = g_const[9];
        const float kGrb2CombShc   = g_const[10];
        const float kSprtyInbGrb2  = g_const[11];
        const float kSosCombGrb2   = g_const[12];
        const float kErkPhosSos    = g_const[13];
        const float kErkPhosPcraf  = g_const[14];
        const float kPcrafDegrad   = g_const[15];
        const float kErkPhosMek    = g_const[16];
        const float kMekDegrad     = g_const[17];
        const float kDuspInbErk    = g_const[18];
        const float kErkDeg        = g_const[19];
        const float kinbBraf       = g_const[20];
        const float kDuspStop      = g_const[21];
        const float kSprtyComeDown = g_const[24];
        const float kdegrad        = g_const[25];
        const float km_Dusp        = g_const[27];
        const float km_Sprty       = g_const[28];
        const float kErkDephos     = g_const[29];
        const float kDuspDeg       = g_const[30];
        const float kHer2_act      = g_const[31];
        const float kHer3_act      = g_const[32];
        const float kbEGFR         = g_const[33];
        const float kbHer2         = g_const[34];
        const float kbHer3         = g_const[35];
        const float kbIGFR         = g_const[36];
        const float kunb           = g_const[37];
        const float kPI3Krec       = g_const[38];
        const float kMTORfb        = g_const[39];
        const float kPIP2          = g_const[40];
        const float kPTEN          = g_const[41];
        const float kAkt           = g_const[42];
        const float kdegAKT        = g_const[43];
        const float kb1            = g_const[44];
        const float k43b1          = g_const[45];
        const float k4ebp1         = g_const[46];
        const float k4ebp1de       = g_const[47];
        const float kKSRphos       = g_const[48];
        const float kKSRdephos     = g_const[49];
        const float kMekByBraf     = g_const[50];
        const float kMekByCraf     = g_const[51];
        const float kMekByKSR      = g_const[52];
        const float kDimerDissoc   = g_const[59];
        const float kPDGFR_act     = g_const[63];
        const float kbPDGFR        = g_const[64];
        const float kS6Kphos       = g_const[65];
        const float kS6Kdephos     = g_const[66];
        const float kRAS_PI3K      = g_const[67];
        const float kERK_IRS       = g_const[68];
        const float kERK_PTEN      = g_const[69];
        const float kAKT_CRAF      = g_const[70];
        const float kS6K_IRS       = g_const[71];
        const float kERK_GAB1      = g_const[72];
        const float kAKT_TSC2      = g_const[73];
        const float kERK_RSK       = g_const[74];
        const float kBRAF_eff      = g_const[75];
        const float tram_ksr       = g_const[76];
        const float kmDuspRatio    = g_const[77];
        const float kmSprtyRatio   = g_const[78];
        const float kDimVem        = g_const[79];
        const float kParaVem       = g_const[80];

        // --- EGFR / Her2 / Her3 receptor modules ---
        sr[0] = -ka1*ys[0] + kr1*ys[1];
        sr[1] =  ka1*ys[0] - kr1*ys[1] - kc1*ys[1];
        sr[2] =  kc1*ys[1] - kDegradEgfr*ys[2] - kErkInbEgfr*ys[28]*ys[2];
        sr[3] = -kHer2_act*ys[3] + kr1*ys[4];
        sr[4] =  kHer2_act*ys[3] - kr1*ys[4] - kc1*ys[4];
        sr[5] =  kc1*ys[4] - kDegradEgfr*ys[5] - kErkInbEgfr*ys[28]*ys[5];
        sr[6] = -kHer3_act*ys[6] + kr1*ys[7];
        sr[7] =  kHer3_act*ys[6] - kr1*ys[7] - kc1*ys[7];
        sr[8] =  kc1*ys[7] - kDegradEgfr*ys[8] - kErkInbEgfr*ys[28]*ys[8];

        // --- Shc / Grb2 / Sos / Ras ---
        float a29 = ka1*ys[2]*ys[9];
        sr[9]  = -a29;
        sr[10] =  a29 - kShcDephos*ys[11]*ys[10];
        sr[11] = -kptpDeg*ys[10]*ys[11];
        sr[12] =  kGrb2CombShc*ys[10]*ys[2] - kSprtyInbGrb2*ys[26]*ys[12];
        sr[13] =  kSosCombGrb2*ys[12]*ys[10] - kErkPhosSos*ys[24]*ys[13];
        float s14 = ka1*ys[13]*ys[14];
        sr[14] = -s14;
        sr[15] =  s14;
        float s16 = ka1*ys[13]*ys[16];
        sr[16] = -s16;
        sr[17] =  s16;
        float s18 = ka1*ys[13]*ys[18];
        float s19 = ka1*ys[19]*ys[20];
        sr[18] = -s18;
        sr[19] =  s18 - s19;
        sr[20] = -s19;

        // --- RAF with vemurafenib paradox ---
        float paradox   = kParaVem * ys[61];
        float akt_craf  = kAKT_CRAF*ys[52]*ys[21];
        float dimF      = kDimVem*ys[24]*ys[21];
        float dimD      = kDimerDissoc*ys[61];
        float craf_fwd  = kpCraf*ys[19]*ys[21];
        float craf_rev  = kErkPhosPcraf*ys[28]*ys[22];
        float craf_deg  = kPcrafDegrad*ys[22]*ys[35];
        float braf_act  = kBRAF_eff*ys[23]*ys[19];
        sr[21] = -craf_fwd + craf_rev + craf_deg - dimF + dimD - akt_craf;
        sr[22] =  craf_fwd - craf_rev - craf_deg + paradox;
        sr[23] = -braf_act - dimF + dimD;
        sr[24] =  braf_act - kinbBraf*ys[24] - dimF + dimD;
        sr[61] =  dimF - dimD - kPcrafDegrad*ys[61]*ys[35];

        // --- MEK / ERK ---
        float raf_to_mek = kpMek*ys[22] + kMekByBraf*ys[24] + kMekByCraf*ys[22];
        float ksr_to_mek = kMekByKSR*ys[60];
        float mek_fwd    = (raf_to_mek + ksr_to_mek)*ys[25];
        float mek_rev    = kErkPhosMek*ys[28]*ys[26];
        float mek_deg    = kMekDegrad*ys[26]*ys[34];
        sr[25] = -mek_fwd + mek_rev + mek_deg;
        sr[26] =  mek_fwd - mek_rev - mek_deg;
        float erk_fwd = kpErk*ys[26]*ys[27];
        float erk_bk  = kDuspInbErk*ys[30]*ys[28] + kErkDeg*ys[28]*ys[33] + kErkDephos*ys[30]*ys[28];
        sr[27] = -erk_fwd + erk_bk;
        sr[28] =  erk_fwd - erk_bk;

        // --- DUSP / Sprouty feedback ---
        float denom_dusp = 1.0f + kmDuspRatio*ys[28];
        sr[29] = km_Dusp*ys[28]/(denom_dusp + EPS) - kDuspStop*ys[29]*ys[36] - kDuspDeg*ys[29]*ys[28];
        sr[30] = -kDuspStop*ys[29]*ys[30];
        float denom_spry = 1.0f + kmSprtyRatio*ys[28];
        float spry_dn = kSprtyComeDown*ys[31]*ys[32];
        sr[31] = km_Sprty*ys[28]/(denom_spry + EPS) - spry_dn;
        sr[32] = -spry_dn;
        sr[33] = -kErkDeg*ys[28]*ys[33];
        sr[34] = -mek_deg;
        sr[35] = -craf_deg;
        sr[36] = -kDuspStop*ys[29]*ys[36];

        // --- IGFR / IRS ---
        sr[37] = -ka1*ys[37] + kr1*ys[38];
        sr[38] =  ka1*ys[37] - kr1*ys[38] - kc1*ys[38];
        sr[39] =  kc1*ys[38] - kErkInbEgfr*ys[28]*ys[39];
        float erk_irs = kERK_IRS*ys[28]*ys[41];
        float s6k_irs = kS6K_IRS*ys[66]*ys[41];
        float irs_fwd = ka1*ys[2]*ys[40];
        sr[40] = -irs_fwd + erk_irs + s6k_irs;
        sr[41] =  irs_fwd - erk_irs - s6k_irs;

        // --- p85 binding ---
        float gab1 = 1.0f / (1.0f + kERK_GAB1*ys[28]);
        float bE  = kbEGFR*ys[2]*ys[42]*gab1;
        float bH2 = kbHer2*ys[5]*ys[42]*gab1;
        float bH3 = kbHer3*ys[8]*ys[42]*gab1;
        float bI  = kbIGFR*ys[39]*ys[42];
        float bP  = kbPDGFR*ys[64]*ys[42];
        float sum_p85c = ys[43] + ys[44] + ys[45] + ys[46] + ys[67];
        sr[42] = -bE - bH2 - bH3 - bI - bP + kunb*sum_p85c;
        sr[43] = bE  - kunb*ys[43];
        sr[44] = bH2 - kunb*ys[44];
        sr[45] = bH3 - kunb*ys[45];
        sr[46] = bI  - kunb*ys[46];
        sr[67] = bP  - kunb*ys[67];

        // --- PI3K / AKT / mTOR axis ---
        float pi3k_act = kPI3Krec*sum_p85c*ys[47] + kRAS_PI3K*ys[15]*ys[47];
        float mtor_fb  = kMTORfb*ys[56]*ys[48];
        sr[47] = -pi3k_act + mtor_fb;
        sr[48] =  pi3k_act - mtor_fb;
        float pip_fwd = kPIP2*ys[48]*ys[49];
        float pip_rev = kPTEN*ys[51]*ys[50];
        sr[49] = -pip_fwd + pip_rev;
        sr[50] =  pip_fwd - pip_rev;
        sr[51] = kERK_PTEN*ys[28] - kdegrad*ys[51];
        float akt_fwd = kAkt*ys[50]*ys[53];
        float akt_rev = kdegAKT*ys[52];
        sr[52] =  akt_fwd - akt_rev;
        sr[53] = -akt_fwd + akt_rev;
        float tsc = kAKT_TSC2*ys[52]*ys[54];
        sr[54] = -tsc;
        sr[55] =  tsc - kdegrad*ys[55];
        float mtor_fwd = kb1*ys[52]*ys[57];
        float mtor_rev = k43b1*ys[56];
        sr[56] =  mtor_fwd - mtor_rev;
        sr[57] = -mtor_fwd + mtor_rev;
        float ebp_fwd = k4ebp1*ys[56]*ys[58];
        float ebp_rev = k4ebp1de*ys[59];
        sr[58] = -ebp_fwd + ebp_rev;
        sr[59] =  ebp_fwd - ebp_rev;

        // --- KSR with trametinib hill factor ---
        float ksr_fwd = kKSRphos*ys[19]*ys[62]*tram_ksr;
        float ksr_rev = kKSRdephos*ys[60];
        sr[60] =  ksr_fwd - ksr_rev;
        sr[62] = -ksr_fwd + ksr_rev;

        // --- PDGFR ---
        sr[63] = -kPDGFR_act*ys[63];
        sr[64] =  kPDGFR_act*ys[63] - kDegradEgfr*ys[64];

        // --- S6K ---
        float s6_fwd = kS6Kphos*ys[56]*ys[65];
        float rsk    = kERK_RSK*ys[28]*ys[65];
        float s6_rev = kS6Kdephos*ys[66];
        sr[65] = -s6_fwd + s6_rev - rsk;
        sr[66] =  s6_fwd - s6_rev + rsk;
    }
    __syncwarp();

    // ---- Phase 3: coalesced smem -> global ----
    {
        float* gdst = out + (size_t)rowStart * NSTATE;
        #pragma unroll 4
        for (int f = lane; f < FLOATS_PER_WARP; f += 32) {
            if (f < nf) {
                int r = f / NSTATE;
                int c = f - r * NSTATE;
                gdst[f] = s[r * ROWPAD + c];
            }
        }
    }
}

extern "C" void kernel_launch(void* const* d_in, const int* in_sizes, int n_in,
                              void* d_out, int out_size) {
    // inputs per metadata order: t (1), y (B*68), params (75)
    const float* y      = (const float*)d_in[1];
    const float* params = (const float*)d_in[2];
    float* out = (float*)d_out;

    int n = in_sizes[1] / NSTATE;  // number of rows (B)

    setup_consts_kernel<<<1, 96>>>(params);

    int blocks = (n + THREADS - 1) / THREADS;
    mapk_rhs_kernel<<<blocks, THREADS>>>(y, out, n);
}

// round 3
// speedup vs baseline: 2.0351x; 2.0351x over previous
#include <cuda_runtime.h>

#define EPS 1e-10f
#define NSTATE 68
#define NF4 17                      // 68 floats = 17 float4
#define COLSTRIDE 33                // 33 % 8 == 1 -> conflict-free bank walk
#define WARPS_PER_BLOCK 4
#define THREADS (WARPS_PER_BLOCK * 32)

// Compute the 68 derivatives for one row. ys/d are register arrays.
__device__ __forceinline__ void compute_rhs(const float* __restrict__ params,
                                            const float* ys, float* d) {
    // ---- raw params (broadcast loads, L1-resident) ----
    const float ka1            = __ldg(&params[0]);
    const float kr1            = __ldg(&params[1]);
    const float kc1            = __ldg(&params[2]);
    const float kpCraf         = __ldg(&params[3]);
    const float kpMek          = __ldg(&params[4]);
    const float kpErk          = __ldg(&params[5]);
    const float kDegradEgfr    = __ldg(&params[6]);
    const float kErkInbEgfr    = __ldg(&params[7]);
    const float kShcDephos     = __ldg(&params[8]);
    const float kptpDeg        = __ldg(&params[9]);
    const float kGrb2CombShc   = __ldg(&params[10]);
    const float kSprtyInbGrb2  = __ldg(&params[11]);
    const float kSosCombGrb2   = __ldg(&params[12]);
    const float kErkPhosSos    = __ldg(&params[13]);
    const float kErkPhosPcraf  = __ldg(&params[14]);
    const float kPcrafDegrad   = __ldg(&params[15]);
    const float kErkPhosMek    = __ldg(&params[16]);
    const float kMekDegrad     = __ldg(&params[17]);
    const float kDuspInbErk    = __ldg(&params[18]);
    const float kErkDeg        = __ldg(&params[19]);
    const float kinbBraf       = __ldg(&params[20]);
    const float kDuspStop      = __ldg(&params[21]);
    const float kDusps         = __ldg(&params[22]);
    const float kSproutyForm   = __ldg(&params[23]);
    const float kSprtyComeDown = __ldg(&params[24]);
    const float kdegrad        = __ldg(&params[25]);
    const float km_Dusp        = __ldg(&params[27]);
    const float km_Sprty       = __ldg(&params[28]);
    const float kErkDephos     = __ldg(&params[29]);
    const float kDuspDeg       = __ldg(&params[30]);
    const float kHer2_act      = __ldg(&params[31]);
    const float kHer3_act      = __ldg(&params[32]);
    const float kbEGFR         = __ldg(&params[33]);
    const float kbHer2         = __ldg(&params[34]);
    const float kbHer3         = __ldg(&params[35]);
    const float kbIGFR         = __ldg(&params[36]);
    const float kunb           = __ldg(&params[37]);
    const float kPI3Krec       = __ldg(&params[38]);
    const float kMTORfb        = __ldg(&params[39]);
    const float kPIP2          = __ldg(&params[40]);
    const float kPTEN          = __ldg(&params[41]);
    const float kAkt           = __ldg(&params[42]);
    const float kdegAKT        = __ldg(&params[43]);
    const float kb1            = __ldg(&params[44]);
    const float k43b1          = __ldg(&params[45]);
    const float k4ebp1         = __ldg(&params[46]);
    const float k4ebp1de       = __ldg(&params[47]);
    const float kKSRphos       = __ldg(&params[48]);
    const float kKSRdephos     = __ldg(&params[49]);
    const float kMekByBraf     = __ldg(&params[50]);
    const float kMekByCraf     = __ldg(&params[51]);
    const float kMekByKSR      = __ldg(&params[52]);
    const float Tram           = __ldg(&params[53]);
    const float K_tram_KSR     = __ldg(&params[55]);
    const float n_tram         = __ldg(&params[56]);
    const float Vem            = __ldg(&params[57]);
    const float kDimerForm     = __ldg(&params[58]);
    const float kDimerDissoc   = __ldg(&params[59]);
    const float kParadoxCRAF   = __ldg(&params[60]);
    const float IC50_vem       = __ldg(&params[61]);
    const float Hill_n_vem     = __ldg(&params[62]);
    const float kPDGFR_act     = __ldg(&params[63]);
    const float kbPDGFR        = __ldg(&params[64]);
    const float kS6Kphos       = __ldg(&params[65]);
    const float kS6Kdephos     = __ldg(&params[66]);
    const float kRAS_PI3K      = __ldg(&params[67]);
    const float kERK_IRS       = __ldg(&params[68]);
    const float kERK_PTEN      = __ldg(&params[69]);
    const float kAKT_CRAF      = __ldg(&params[70]);
    const float kS6K_IRS       = __ldg(&params[71]);
    const float kERK_GAB1      = __ldg(&params[72]);
    const float kAKT_TSC2      = __ldg(&params[73]);
    const float kERK_RSK       = __ldg(&params[74]);

    // ---- derived (uniform across threads; hidden under memory latency) ----
    const float ic50n    = powf(IC50_vem, Hill_n_vem);
    const float vemn     = powf(Vem, Hill_n_vem);
    const float kBRAF_eff = ka1 * ic50n / (ic50n + vemn + EPS);
    const float ktn      = powf(K_tram_KSR, n_tram);
    const float tn       = powf(Tram, n_tram);
    const float tram_ksr = ktn / (ktn + tn + EPS);
    const float kmDuspRatio  = km_Dusp  / (kDusps + EPS);
    const float kmSprtyRatio = km_Sprty / (kSproutyForm + EPS);
    const float kDimVem  = kDimerForm * Vem;
    const float kParaVem = kParadoxCRAF * Vem;

    // --- EGFR / Her2 / Her3 receptor modules ---
    d[0] = -ka1*ys[0] + kr1*ys[1];
    d[1] =  ka1*ys[0] - kr1*ys[1] - kc1*ys[1];
    d[2] =  kc1*ys[1] - kDegradEgfr*ys[2] - kErkInbEgfr*ys[28]*ys[2];
    d[3] = -kHer2_act*ys[3] + kr1*ys[4];
    d[4] =  kHer2_act*ys[3] - kr1*ys[4] - kc1*ys[4];
    d[5] =  kc1*ys[4] - kDegradEgfr*ys[5] - kErkInbEgfr*ys[28]*ys[5];
    d[6] = -kHer3_act*ys[6] + kr1*ys[7];
    d[7] =  kHer3_act*ys[6] - kr1*ys[7] - kc1*ys[7];
    d[8] =  kc1*ys[7] - kDegradEgfr*ys[8] - kErkInbEgfr*ys[28]*ys[8];

    // --- Shc / Grb2 / Sos / Ras ---
    float a29 = ka1*ys[2]*ys[9];
    d[9]  = -a29;
    d[10] =  a29 - kShcDephos*ys[11]*ys[10];
    d[11] = -kptpDeg*ys[10]*ys[11];
    d[12] =  kGrb2CombShc*ys[10]*ys[2] - kSprtyInbGrb2*ys[26]*ys[12];
    d[13] =  kSosCombGrb2*ys[12]*ys[10] - kErkPhosSos*ys[24]*ys[13];
    float s14 = ka1*ys[13]*ys[14];
    d[14] = -s14;
    d[15] =  s14;
    float s16 = ka1*ys[13]*ys[16];
    d[16] = -s16;
    d[17] =  s16;
    float s18 = ka1*ys[13]*ys[18];
    float s19 = ka1*ys[19]*ys[20];
    d[18] = -s18;
    d[19] =  s18 - s19;
    d[20] = -s19;

    // --- RAF with vemurafenib paradox ---
    float paradox   = kParaVem * ys[61];
    float akt_craf  = kAKT_CRAF*ys[52]*ys[21];
    float dimF      = kDimVem*ys[24]*ys[21];
    float dimD      = kDimerDissoc*ys[61];
    float craf_fwd  = kpCraf*ys[19]*ys[21];
    float craf_rev  = kErkPhosPcraf*ys[28]*ys[22];
    float craf_deg  = kPcrafDegrad*ys[22]*ys[35];
    float braf_act  = kBRAF_eff*ys[23]*ys[19];
    d[21] = -craf_fwd + craf_rev + craf_deg - dimF + dimD - akt_craf;
    d[22] =  craf_fwd - craf_rev - craf_deg + paradox;
    d[23] = -braf_act - dimF + dimD;
    d[24] =  braf_act - kinbBraf*ys[24] - dimF + dimD;
    d[61] =  dimF - dimD - kPcrafDegrad*ys[61]*ys[35];

    // --- MEK / ERK ---
    float raf_to_mek = kpMek*ys[22] + kMekByBraf*ys[24] + kMekByCraf*ys[22];
    float ksr_to_mek = kMekByKSR*ys[60];
    float mek_fwd    = (raf_to_mek + ksr_to_mek)*ys[25];
    float mek_rev    = kErkPhosMek*ys[28]*ys[26];
    float mek_deg    = kMekDegrad*ys[26]*ys[34];
    d[25] = -mek_fwd + mek_rev + mek_deg;
    d[26] =  mek_fwd - mek_rev - mek_deg;
    float erk_fwd = kpErk*ys[26]*ys[27];
    float erk_bk  = kDuspInbErk*ys[30]*ys[28] + kErkDeg*ys[28]*ys[33] + kErkDephos*ys[30]*ys[28];
    d[27] = -erk_fwd + erk_bk;
    d[28] =  erk_fwd - erk_bk;

    // --- DUSP / Sprouty feedback ---
    float denom_dusp = 1.0f + kmDuspRatio*ys[28];
    d[29] = km_Dusp*ys[28]/(denom_dusp + EPS) - kDuspStop*ys[29]*ys[36] - kDuspDeg*ys[29]*ys[28];
    d[30] = -kDuspStop*ys[29]*ys[30];
    float denom_spry = 1.0f + kmSprtyRatio*ys[28];
    float spry_dn = kSprtyComeDown*ys[31]*ys[32];
    d[31] = km_Sprty*ys[28]/(denom_spry + EPS) - spry_dn;
    d[32] = -spry_dn;
    d[33] = -kErkDeg*ys[28]*ys[33];
    d[34] = -mek_deg;
    d[35] = -craf_deg;
    d[36] = -kDuspStop*ys[29]*ys[36];

    // --- IGFR / IRS ---
    d[37] = -ka1*ys[37] + kr1*ys[38];
    d[38] =  ka1*ys[37] - kr1*ys[38] - kc1*ys[38];
    d[39] =  kc1*ys[38] - kErkInbEgfr*ys[28]*ys[39];
    float erk_irs = kERK_IRS*ys[28]*ys[41];
    float s6k_irs = kS6K_IRS*ys[66]*ys[41];
    float irs_fwd = ka1*ys[2]*ys[40];
    d[40] = -irs_fwd + erk_irs + s6k_irs;
    d[41] =  irs_fwd - erk_irs - s6k_irs;

    // --- p85 binding ---
    float gab1 = 1.0f / (1.0f + kERK_GAB1*ys[28]);
    float bE  = kbEGFR*ys[2]*ys[42]*gab1;
    float bH2 = kbHer2*ys[5]*ys[42]*gab1;
    float bH3 = kbHer3*ys[8]*ys[42]*gab1;
    float bI  = kbIGFR*ys[39]*ys[42];
    float bP  = kbPDGFR*ys[64]*ys[42];
    float sum_p85c = ys[43] + ys[44] + ys[45] + ys[46] + ys[67];
    d[42] = -bE - bH2 - bH3 - bI - bP + kunb*sum_p85c;
    d[43] = bE  - kunb*ys[43];
    d[44] = bH2 - kunb*ys[44];
    d[45] = bH3 - kunb*ys[45];
    d[46] = bI  - kunb*ys[46];
    d[67] = bP  - kunb*ys[67];

    // --- PI3K / AKT / mTOR axis ---
    float pi3k_act = kPI3Krec*sum_p85c*ys[47] + kRAS_PI3K*ys[15]*ys[47];
    float mtor_fb  = kMTORfb*ys[56]*ys[48];
    d[47] = -pi3k_act + mtor_fb;
    d[48] =  pi3k_act - mtor_fb;
    float pip_fwd = kPIP2*ys[48]*ys[49];
    float pip_rev = kPTEN*ys[51]*ys[50];
    d[49] = -pip_fwd + pip_rev;
    d[50] =  pip_fwd - pip_rev;
    d[51] = kERK_PTEN*ys[28] - kdegrad*ys[51];
    float akt_fwd = kAkt*ys[50]*ys[53];
    float akt_rev = kdegAKT*ys[52];
    d[52] =  akt_fwd - akt_rev;
    d[53] = -akt_fwd + akt_rev;
    float tsc = kAKT_TSC2*ys[52]*ys[54];
    d[54] = -tsc;
    d[55] =  tsc - kdegrad*ys[55];
    float mtor_fwd = kb1*ys[52]*ys[57];
    float mtor_rev = k43b1*ys[56];
    d[56] =  mtor_fwd - mtor_rev;
    d[57] = -mtor_fwd + mtor_rev;
    float ebp_fwd = k4ebp1*ys[56]*ys[58];
    float ebp_rev = k4ebp1de*ys[59];
    d[58] = -ebp_fwd + ebp_rev;
    d[59] =  ebp_fwd - ebp_rev;

    // --- KSR with trametinib hill factor ---
    float ksr_fwd = kKSRphos*ys[19]*ys[62]*tram_ksr;
    float ksr_rev = kKSRdephos*ys[60];
    d[60] =  ksr_fwd - ksr_rev;
    d[62] = -ksr_fwd + ksr_rev;

    // --- PDGFR ---
    d[63] = -kPDGFR_act*ys[63];
    d[64] =  kPDGFR_act*ys[63] - kDegradEgfr*ys[64];

    // --- S6K ---
    float s6_fwd = kS6Kphos*ys[56]*ys[65];
    float rsk    = kERK_RSK*ys[28]*ys[65];
    float s6_rev = kS6Kdephos*ys[66];
    d[65] = -s6_fwd + s6_rev - rsk;
    d[66] =  s6_fwd - s6_rev + rsk;
}

__global__ __launch_bounds__(THREADS)
void mapk_rhs_kernel(const float* __restrict__ y, const float* __restrict__ params,
                     float* __restrict__ out, int n) {
    // Per-warp float4 tile, column-major with stride 33 (conflict-free).
    __shared__ float4 stage[WARPS_PER_BLOCK][NF4 * COLSTRIDE];

    const int lane = threadIdx.x & 31;
    const int warp = threadIdx.x >> 5;
    const int rowStart = blockIdx.x * THREADS + warp * 32;
    if (rowStart >= n) return;
    const int rowsHere = min(32, n - rowStart);

    float4* sm = stage[warp];

    if (rowsHere == 32) {
        const float4* gsrc = reinterpret_cast<const float4*>(y) + (size_t)rowStart * NF4;

        // ---- Phase 1: coalesced LDG.128 -> transposed smem tile ----
        #pragma unroll
        for (int j = 0; j < NF4; j++) {
            int i = j * 32 + lane;          // global f4 index within warp tile
            int r = i / NF4;                // row within tile
            int c = i - r * NF4;            // f4-column within row
            float4 v = __ldg(&gsrc[i]);
            v.x = fmaxf(v.x, 0.0f);
            v.y = fmaxf(v.y, 0.0f);
            v.z = fmaxf(v.z, 0.0f);
            v.w = fmaxf(v.w, 0.0f);
            sm[c * COLSTRIDE + r] = v;
        }
        __syncwarp();

        // ---- Phase 2: each thread owns row = lane; all accesses conflict-free ----
        {
            float ys[NSTATE];
            float4* ysv = reinterpret_cast<float4*>(ys);
            #pragma unroll
            for (int c = 0; c < NF4; c++) ysv[c] = sm[c * COLSTRIDE + lane];

            float d[NSTATE];
            compute_rhs(params, ys, d);

            const float4* dv = reinterpret_cast<const float4*>(d);
            #pragma unroll
            for (int c = 0; c < NF4; c++) sm[c * COLSTRIDE + lane] = dv[c];
        }
        __syncwarp();

        // ---- Phase 3: transposed smem tile -> coalesced STG.128 ----
        float4* gdst = reinterpret_cast<float4*>(out) + (size_t)rowStart * NF4;
        #pragma unroll
        for (int j = 0; j < NF4; j++) {
            int i = j * 32 + lane;
            int r = i / NF4;
            int c = i - r * NF4;
            gdst[i] = sm[c * COLSTRIDE + r];
        }
    } else {
        // ---- Tail path (rows < 32): direct per-row float4 access ----
        if (lane < rowsHere) {
            const int row = rowStart + lane;
            const float4* yv = reinterpret_cast<const float4*>(y) + (size_t)row * NF4;
            float ys[NSTATE];
            float4* ysv = reinterpret_cast<float4*>(ys);
            #pragma unroll
            for (int c = 0; c < NF4; c++) {
                float4 v = __ldg(&yv[c]);
                v.x = fmaxf(v.x, 0.0f);
                v.y = fmaxf(v.y, 0.0f);
                v.z = fmaxf(v.z, 0.0f);
                v.w = fmaxf(v.w, 0.0f);
                ysv[c] = v;
            }
            float d[NSTATE];
            compute_rhs(params, ys, d);
            float4* ov = reinterpret_cast<float4*>(out) + (size_t)row * NF4;
            const float4* dv = reinterpret_cast<const float4*>(d);
            #pragma unroll
            for (int c = 0; c < NF4; c++) ov[c] = dv[c];
        }
    }
}

extern "C" void kernel_launch(void* const* d_in, const int* in_sizes, int n_in,
                              void* d_out, int out_size) {
    // inputs per metadata order: t (1), y (B*68), params (75)
    const float* y      = (const float*)d_in[1];
    const float* params = (const float*)d_in[2];
    float* out = (float*)d_out;

    int n = in_sizes[1] / NSTATE;   // number of rows (B)

    int blocks = (n + THREADS - 1) / THREADS;
    mapk_rhs_kernel<<<blocks, THREADS>>>(y, params, out, n);
}